// round 15
// baseline (speedup 1.0000x reference)
#include <cuda_runtime.h>

#define FULLMASK 0xFFFFFFFFu

// One warp per 4096-element SEGMENT of a (b,c) row. Segments independent via
// a decayed warm-up halo (g^halo < 1e-10 => exact at fp32; clamps to row
// start / exact full-scan fallback if g ~ 1). Tile = 512 elements: lane owns
// 16 contiguous elements (four float4s), loaded as one 4x LDG.128 burst at
// the top of each iteration (MLP=4, no software prefetch to mis-schedule).
//   per-lane 16-elem chain tail -> warp Kogge-Stone over lane tails (ratio
//   g^16) -> cross-tile carry with g^512 -> outputs reconstructed with the
//   exact serial recurrence seeded from the scan state, stored as 4 STG.128.
__global__ void __launch_bounds__(64)
ema_scan_t512_kernel(const float4* __restrict__ x4,
                     const float* __restrict__ w,
                     float4* __restrict__ out4,
                     int Cdim, int T, int nrows, int nseg)
{
    constexpr int SEG_TILES = 8;              // 8 * 512 = 4096 elems/segment
    const int warp = threadIdx.x >> 5;
    const int lane = threadIdx.x & 31;
    const int gw   = blockIdx.x * 2 + warp;   // global segment id
    const int row  = gw / nseg;
    const int seg  = gw - row * nseg;
    if (row >= nrows) return;

    const float g   = __ldg(&w[row % Cdim]);
    const float omg = 1.0f - g;

    const float g2   = g * g;
    const float g4   = g2 * g2;
    const float g8   = g4 * g4;
    const float g16  = g8 * g8;               // lane-step ratio
    const float g32  = g16 * g16;
    const float g64  = g32 * g32;
    const float g128 = g64 * g64;
    const float g256 = g128 * g128;
    const float g512 = g256 * g256;           // tile-step ratio

    // g^(16*lane) by binary decomposition
    float pl = 1.0f;
    if (lane & 1)  pl *= g16;
    if (lane & 2)  pl *= g32;
    if (lane & 4)  pl *= g64;
    if (lane & 8)  pl *= g128;
    if (lane & 16) pl *= g256;

    // warm-up tiles: g^(512*wt) < 1e-10; exact fallback if g ~ 1
    int wt;
    if (g > 0.0f && g < 0.9999f)
        wt = (int)((-23.03f * (1.0f / 512.0f)) / __logf(g)) + 1;
    else
        wt = 0x3fffffff;
    const int seg_tile0 = seg * SEG_TILES;
    if (wt > seg_tile0) wt = seg_tile0;
    if (wt < 0) wt = 0;

    const float4* __restrict__ xin  = x4   + (size_t)row * (T >> 2);
    float4*       __restrict__ yout = out4 + (size_t)row * (T >> 2);

    const int tile_begin = seg_tile0 - wt;
    const int count      = wt + SEG_TILES;

    float C = 0.0f;
    int base = tile_begin * 128 + 4 * lane;   // float4 index of lane's chunk

    #pragma unroll 1
    for (int t = 0; t < count; ++t) {
        // 4-load burst: 2 KB in flight for this warp
        float4 a0 = __ldcs(xin + base);
        float4 a1 = __ldcs(xin + base + 1);
        float4 a2 = __ldcs(xin + base + 2);
        float4 a3 = __ldcs(xin + base + 3);

        // per-lane chain tail over 16 contiguous elements
        float l = a0.x * omg;
        l = fmaf(g, l, a0.y * omg);
        l = fmaf(g, l, a0.z * omg);
        l = fmaf(g, l, a0.w * omg);
        l = fmaf(g, l, a1.x * omg);
        l = fmaf(g, l, a1.y * omg);
        l = fmaf(g, l, a1.z * omg);
        l = fmaf(g, l, a1.w * omg);
        l = fmaf(g, l, a2.x * omg);
        l = fmaf(g, l, a2.y * omg);
        l = fmaf(g, l, a2.z * omg);
        l = fmaf(g, l, a2.w * omg);
        l = fmaf(g, l, a3.x * omg);
        l = fmaf(g, l, a3.y * omg);
        l = fmaf(g, l, a3.z * omg);
        l = fmaf(g, l, a3.w * omg);

        // warp inclusive scan of lane tails, ratio g^16
        float v = l, tv;
        tv = __shfl_up_sync(FULLMASK, v, 1);  if (lane >= 1)  v = fmaf(g16,  tv, v);
        tv = __shfl_up_sync(FULLMASK, v, 2);  if (lane >= 2)  v = fmaf(g32,  tv, v);
        tv = __shfl_up_sync(FULLMASK, v, 4);  if (lane >= 4)  v = fmaf(g64,  tv, v);
        tv = __shfl_up_sync(FULLMASK, v, 8);  if (lane >= 8)  v = fmaf(g128, tv, v);
        tv = __shfl_up_sync(FULLMASK, v, 16); if (lane >= 16) v = fmaf(g256, tv, v);

        // exclusive carry from earlier lanes
        float cL = __shfl_up_sync(FULLMASK, v, 1);
        if (lane == 0) cL = 0.0f;

        // cross-tile carry source (read before outputs clobber anything)
        const float v31 = __shfl_sync(FULLMASK, v, 31);

        if (t >= wt) {
            // EMA state just before this lane's first element; exact serial
            // reconstruction of the 16 outputs, in place
            float y = fmaf(pl, C, cL);
            y = fmaf(g, y, a0.x * omg);  a0.x = y;
            y = fmaf(g, y, a0.y * omg);  a0.y = y;
            y = fmaf(g, y, a0.z * omg);  a0.z = y;
            y = fmaf(g, y, a0.w * omg);  a0.w = y;
            y = fmaf(g, y, a1.x * omg);  a1.x = y;
            y = fmaf(g, y, a1.y * omg);  a1.y = y;
            y = fmaf(g, y, a1.z * omg);  a1.z = y;
            y = fmaf(g, y, a1.w * omg);  a1.w = y;
            y = fmaf(g, y, a2.x * omg);  a2.x = y;
            y = fmaf(g, y, a2.y * omg);  a2.y = y;
            y = fmaf(g, y, a2.z * omg);  a2.z = y;
            y = fmaf(g, y, a2.w * omg);  a2.w = y;
            y = fmaf(g, y, a3.x * omg);  a3.x = y;
            y = fmaf(g, y, a3.y * omg);  a3.y = y;
            y = fmaf(g, y, a3.z * omg);  a3.z = y;
            y = fmaf(g, y, a3.w * omg);  a3.w = y;
            __stcs(yout + base,     a0);
            __stcs(yout + base + 1, a1);
            __stcs(yout + base + 2, a2);
            __stcs(yout + base + 3, a3);
        }

        C = fmaf(g512, C, v31);
        base += 128;
    }
}

extern "C" void kernel_launch(void* const* d_in, const int* in_sizes, int n_in,
                              void* d_out, int out_size)
{
    const float4* x4 = (const float4*)d_in[0];
    const float*  w  = (const float*)d_in[1];
    float4* out4 = (float4*)d_out;

    const int Cdim  = in_sizes[1];          // 512
    const int T     = 16384;                // fixed problem shape
    const int nrows = in_sizes[0] / T;      // B*C = 4096
    const int nseg  = T / 4096;             // 4 segments per row

    const int total_warps     = nrows * nseg;   // 16384
    const int warps_per_block = 2;
    dim3 block(32 * warps_per_block);           // 64 threads
    dim3 grid((total_warps + warps_per_block - 1) / warps_per_block);
    ema_scan_t512_kernel<<<grid, block>>>(x4, w, out4, Cdim, T, nrows, nseg);
}

// round 17
// speedup vs baseline: 1.0868x; 1.0868x over previous
#include <cuda_runtime.h>

#define FULLMASK 0xFFFFFFFFu

// One warp per 4096-element SEGMENT of a (b,c) row. Segments independent via
// a decayed warm-up halo (g^halo < 1e-10 => exact at fp32; clamps to row
// start / exact full-scan fallback if g ~ 1).
// Tile = 256 elements with INTERLEAVED lane ownership: lane owns float4
// slot [lane] (elements 4*lane..4*lane+3 of the tile's first half) and slot
// [32+lane] (same positions in the second half). Every LDG.128/STG.128 is
// therefore stride-16B across lanes = perfectly coalesced (minimum L1
// wavefronts), unlike the paired layout whose stride-32B doubles L1 work.
// Scan: per half, lane-local 4-elem chain -> two INDEPENDENT Kogge-Stone
// scans (ratio g^4) interleaved for ILP -> serial seeding between halves
// (4 FMAs) -> cross-tile carry with g^128 per half. Outputs reconstructed
// in place with the exact serial recurrence. Prefetch depth 1.
__global__ void __launch_bounds__(64)
ema_scan_il_kernel(const float4* __restrict__ x4,
                   const float* __restrict__ w,
                   float4* __restrict__ out4,
                   int Cdim, int T, int nrows, int nseg)
{
    constexpr int SEG_TILES = 16;             // 16 * 256 = 4096 elems/segment
    const int warp = threadIdx.x >> 5;
    const int lane = threadIdx.x & 31;
    const int gw   = blockIdx.x * 2 + warp;   // global segment id
    const int row  = gw / nseg;
    const int seg  = gw - row * nseg;
    if (row >= nrows) return;

    const float g   = __ldg(&w[row % Cdim]);
    const float omg = 1.0f - g;

    const float g2   = g * g;
    const float g4   = g2 * g2;               // lane-step ratio (per half)
    const float g8   = g4 * g4;
    const float g16  = g8 * g8;
    const float g32  = g16 * g16;
    const float g64  = g32 * g32;
    const float g128 = g64 * g64;             // half-step ratio

    // g^(4*lane) by binary decomposition
    float pl = 1.0f;
    if (lane & 1)  pl *= g4;
    if (lane & 2)  pl *= g8;
    if (lane & 4)  pl *= g16;
    if (lane & 8)  pl *= g32;
    if (lane & 16) pl *= g64;

    // warm-up tiles: g^(256*wt) < 1e-10; exact fallback if g ~ 1
    int wt;
    if (g > 0.0f && g < 0.9999f)
        wt = (int)((-23.03f * (1.0f / 256.0f)) / __logf(g)) + 1;
    else
        wt = 0x3fffffff;
    const int seg_tile0 = seg * SEG_TILES;
    if (wt > seg_tile0) wt = seg_tile0;
    if (wt < 0) wt = 0;

    const float4* __restrict__ xin  = x4   + (size_t)row * (T >> 2);
    float4*       __restrict__ yout = out4 + (size_t)row * (T >> 2);

    const int tile_begin = seg_tile0 - wt;
    const int count      = wt + SEG_TILES;

    float C = 0.0f;                           // EMA state at end of prev tile
    int base = tile_begin * 64 + lane;        // lane's slot in half 0

    // prime prefetch: half0 slot [lane], half1 slot [32+lane]
    float4 a0 = __ldcs(xin + base);
    float4 a1 = __ldcs(xin + base + 32);

    #pragma unroll 1
    for (int t = 0; t < count; ++t) {
        // prefetch next tile while this one is scanned
        float4 n0 = a0, n1 = a1;
        if (t + 1 < count) {
            n0 = __ldcs(xin + base + 64);
            n1 = __ldcs(xin + base + 96);
        }

        // lane-local 4-elem chain tails for both halves (independent -> ILP)
        float l0 = a0.x * omg;
        float l1 = a1.x * omg;
        l0 = fmaf(g, l0, a0.y * omg);  l1 = fmaf(g, l1, a1.y * omg);
        l0 = fmaf(g, l0, a0.z * omg);  l1 = fmaf(g, l1, a1.z * omg);
        l0 = fmaf(g, l0, a0.w * omg);  l1 = fmaf(g, l1, a1.w * omg);

        // two interleaved Kogge-Stone scans, ratio g^4
        float v0 = l0, v1 = l1, t0, t1;
        t0 = __shfl_up_sync(FULLMASK, v0, 1);
        t1 = __shfl_up_sync(FULLMASK, v1, 1);
        if (lane >= 1)  { v0 = fmaf(g4,  t0, v0); v1 = fmaf(g4,  t1, v1); }
        t0 = __shfl_up_sync(FULLMASK, v0, 2);
        t1 = __shfl_up_sync(FULLMASK, v1, 2);
        if (lane >= 2)  { v0 = fmaf(g8,  t0, v0); v1 = fmaf(g8,  t1, v1); }
        t0 = __shfl_up_sync(FULLMASK, v0, 4);
        t1 = __shfl_up_sync(FULLMASK, v1, 4);
        if (lane >= 4)  { v0 = fmaf(g16, t0, v0); v1 = fmaf(g16, t1, v1); }
        t0 = __shfl_up_sync(FULLMASK, v0, 8);
        t1 = __shfl_up_sync(FULLMASK, v1, 8);
        if (lane >= 8)  { v0 = fmaf(g32, t0, v0); v1 = fmaf(g32, t1, v1); }
        t0 = __shfl_up_sync(FULLMASK, v0, 16);
        t1 = __shfl_up_sync(FULLMASK, v1, 16);
        if (lane >= 16) { v0 = fmaf(g64, t0, v0); v1 = fmaf(g64, t1, v1); }

        // exclusive carries + tail values for both halves
        float cL0 = __shfl_up_sync(FULLMASK, v0, 1);
        float cL1 = __shfl_up_sync(FULLMASK, v1, 1);
        if (lane == 0) { cL0 = 0.0f; cL1 = 0.0f; }
        const float v31_0 = __shfl_sync(FULLMASK, v0, 31);
        const float v31_1 = __shfl_sync(FULLMASK, v1, 31);

        // serial seeding: state before half0 lane, end of half0, etc.
        const float W0   = fmaf(pl, C, cL0);       // state at 4*lane-1 (half0)
        const float Cmid = fmaf(g128, C, v31_0);   // state at end of half0
        const float W1   = fmaf(pl, Cmid, cL1);    // state at 4*lane-1 (half1)
        C = fmaf(g128, Cmid, v31_1);               // state at end of tile

        if (t >= wt) {
            // exact serial reconstruction, in place
            float y = W0;
            y = fmaf(g, y, a0.x * omg);  a0.x = y;
            y = fmaf(g, y, a0.y * omg);  a0.y = y;
            y = fmaf(g, y, a0.z * omg);  a0.z = y;
            y = fmaf(g, y, a0.w * omg);  a0.w = y;
            float z = W1;
            z = fmaf(g, z, a1.x * omg);  a1.x = z;
            z = fmaf(g, z, a1.y * omg);  a1.y = z;
            z = fmaf(g, z, a1.z * omg);  a1.z = z;
            z = fmaf(g, z, a1.w * omg);  a1.w = z;
            __stcs(yout + base,      a0);
            __stcs(yout + base + 32, a1);
        }

        a0 = n0; a1 = n1;
        base += 64;
    }
}

extern "C" void kernel_launch(void* const* d_in, const int* in_sizes, int n_in,
                              void* d_out, int out_size)
{
    const float4* x4 = (const float4*)d_in[0];
    const float*  w  = (const float*)d_in[1];
    float4* out4 = (float4*)d_out;

    const int Cdim  = in_sizes[1];          // 512
    const int T     = 16384;                // fixed problem shape
    const int nrows = in_sizes[0] / T;      // B*C = 4096
    const int nseg  = T / 4096;             // 4 segments per row

    const int total_warps     = nrows * nseg;   // 16384
    const int warps_per_block = 2;
    dim3 block(32 * warps_per_block);           // 64 threads
    dim3 grid((total_warps + warps_per_block - 1) / warps_per_block);
    ema_scan_il_kernel<<<grid, block>>>(x4, w, out4, Cdim, T, nrows, nseg);
}